// round 12
// baseline (speedup 1.0000x reference)
#include <cuda_runtime.h>
#include <cstdint>

// ---------------------------------------------------------------------------
// MemoryAttention R12: selection fused onto MMA accumulators.
//   - warp tile 16q x 32c (as R10); each warp keeps top-32 of its 32-col
//     slice for its 16 queries, directly from D-fragments. NO score smem,
//     NO per-chunk __syncthreads. End-of-loop 4-way merge per query.
//   - mu: 3-deep TMA ring (full=tx barrier, empty=8 warp arrivals).
//   - per-lane select state: cu[16]/ci[16] slots (static indexing) +
//     thr for the lane's own 2 queries; redux.min derives mins on demand.
//   - epilogue: merge -> exact fp32 rescore -> softmax/gather/gate (as R10).
// ---------------------------------------------------------------------------

#define FULLMASK 0xffffffffu

constexpr int NQ  = 8192;
constexpr int NC  = 32768;
constexpr int DK  = 64;
constexpr int QT  = 32;        // queries per CTA
constexpr int CT  = 128;       // centers per chunk
constexpr int NCHUNK = NC / CT;    // 256
constexpr int MUS  = 68;       // mu row stride (floats) inside blob
constexpr int BUFFLOATS = CT + CT * MUS;      // 8832 (hm2 + mu)
constexpr uint32_t BUFBYTES = BUFFLOATS * 4;  // 35328 B

static __device__ float g_hm2[NC];
static __device__ float g_blob[(size_t)NCHUNK * BUFFLOATS];   // ~9 MB

constexpr int RV_OFF = 0;
constexpr int RE_OFF = NQ * 128;
constexpr int G_OFF  = RE_OFF + NQ * 4;

// smem layout (floats)
constexpr int OFF_MBAR = 0;                    // 6 mbarriers (48 B) -> 16 f
constexpr int OFF_BLOB = 16;                   // 3 * 8832 = 26496
constexpr int SMEM_FLOATS = OFF_BLOB + 3 * BUFFLOATS;   // 26512 f = 106048 B

// aliases inside blob region, used AFTER the chunk loop (post-sync):
constexpr int OFF_MV  = OFF_BLOB;              // 32 q * 128 vals   = 4096
constexpr int OFF_MI  = OFF_MV + 4096;         // 32 q * 128 idx    = 4096
constexpr int OFF_TI  = OFF_MI + 4096;         // 32 q * 32 idx     = 1024
constexpr int OFF_SCR = OFF_TI + 1024;         // 8 warps * 64      = 512
// sQ staged in buffer 2 before its first TMA:
constexpr int OFF_Q   = OFF_BLOB + 2 * BUFFLOATS;

__device__ __forceinline__ uint32_t to_tf32(float f) {
    uint32_t u;
    asm("cvt.rna.tf32.f32 %0, %1;" : "=r"(u) : "f"(f));
    return u;
}

__global__ void prep_kernel(const float* __restrict__ mu) {
    int c = blockIdx.x * 256 + threadIdx.x;   // 32768 rows
    const float4* r = reinterpret_cast<const float4*>(mu) + (size_t)c * 16;
    int n = c & 127;
    float* blob = g_blob + (size_t)(c >> 7) * BUFFLOATS;
    float4* w = reinterpret_cast<float4*>(blob + CT + n * MUS);
    float s = 0.f;
#pragma unroll
    for (int j = 0; j < 16; j++) {
        float4 v = r[j];
        s += v.x * v.x + v.y * v.y + v.z * v.z + v.w * v.w;
        float4 t;
        t.x = __uint_as_float(to_tf32(v.x));
        t.y = __uint_as_float(to_tf32(v.y));
        t.z = __uint_as_float(to_tf32(v.z));
        t.w = __uint_as_float(to_tf32(v.w));
        w[j] = t;
    }
    int p  = (n & 7) * 16 + (n >> 3);
    int ws = p ^ (((p >> 4) & 7) << 2);
    blob[ws] = 0.5f * s;
    g_hm2[c] = 0.5f * s;
}

__device__ __forceinline__ unsigned fenc(float f) {
    unsigned u = __float_as_uint(f);
    return (u & 0x80000000u) ? ~u : (u | 0x80000000u);
}
__device__ __forceinline__ float fdec(unsigned u) {
    return (u & 0x80000000u) ? __uint_as_float(u & 0x7fffffffu)
                             : __uint_as_float(~u);
}
__device__ __forceinline__ unsigned redux_min_u32(unsigned v) {
    unsigned r;
    asm("redux.sync.min.u32 %0, %1, 0xffffffff;" : "=r"(r) : "r"(v));
    return r;
}
__device__ __forceinline__ void mma_tf32(float* d, const uint32_t* a,
                                         uint32_t b0, uint32_t b1) {
    asm("mma.sync.aligned.m16n8k8.row.col.f32.tf32.tf32.f32 "
        "{%0,%1,%2,%3}, {%4,%5,%6,%7}, {%8,%9}, {%0,%1,%2,%3};"
        : "+f"(d[0]), "+f"(d[1]), "+f"(d[2]), "+f"(d[3])
        : "r"(a[0]), "r"(a[1]), "r"(a[2]), "r"(a[3]), "r"(b0), "r"(b1));
}
__device__ __forceinline__ void ldsm_x4(uint32_t addr, uint32_t& r0,
                                        uint32_t& r1, uint32_t& r2, uint32_t& r3) {
    asm volatile("ldmatrix.sync.aligned.m8n8.x4.shared.b16 {%0,%1,%2,%3}, [%4];"
                 : "=r"(r0), "=r"(r1), "=r"(r2), "=r"(r3) : "r"(addr));
}
__device__ __forceinline__ void mbar_init(uint32_t addr, uint32_t count) {
    asm volatile("mbarrier.init.shared.b64 [%0], %1;" :: "r"(addr), "r"(count)
                 : "memory");
}
__device__ __forceinline__ void mbar_arrive(uint32_t addr) {
    asm volatile("mbarrier.arrive.release.cta.shared.b64 _, [%0];"
                 :: "r"(addr) : "memory");
}
__device__ __forceinline__ void mbar_expect_tx(uint32_t addr, uint32_t bytes) {
    asm volatile("mbarrier.arrive.expect_tx.shared.b64 _, [%0], %1;"
                 :: "r"(addr), "r"(bytes) : "memory");
}
__device__ __forceinline__ void mbar_wait(uint32_t addr, uint32_t parity) {
    asm volatile(
        "{\n\t"
        ".reg .pred P;\n"
        "W_%=:\n\t"
        "mbarrier.try_wait.parity.acquire.cta.shared::cta.b64 P, [%0], %1, 0x989680;\n\t"
        "@P bra D_%=;\n\t"
        "bra W_%=;\n"
        "D_%=:\n\t"
        "}"
        :: "r"(addr), "r"(parity) : "memory");
}
__device__ __forceinline__ void bulk_g2s(uint32_t dst, const void* src,
                                         uint32_t bytes, uint32_t mbar) {
    asm volatile(
        "cp.async.bulk.shared::cta.global.mbarrier::complete_tx::bytes "
        "[%0], [%1], %2, [%3];"
        :: "r"(dst), "l"(src), "r"(bytes), "r"(mbar) : "memory");
}

// row element j (0..7) of query-row sel (0 = rows tr, 1 = rows tr+8)
#define ROW_GET(RSEL, J) (RSEL ? acc[(J) >> 1][2 + ((J) & 1)] : acc[(J) >> 1][(J) & 1])
#define ROW_SET(RSEL, J, VAL) do { \
    if (RSEL) acc[(J) >> 1][2 + ((J) & 1)] = (VAL); \
    else      acc[(J) >> 1][(J) & 1] = (VAL); } while (0)

__global__ __launch_bounds__(256, 2)
void ma_kernel(const float* __restrict__ x,
               const float* __restrict__ q_tilde,
               const float* __restrict__ g_prior,
               const float* __restrict__ mu,
               const float* __restrict__ V,
               const float* __restrict__ E,
               const float* __restrict__ sig,
               const float* __restrict__ Wg,
               const float* __restrict__ Wgb,
               const float* __restrict__ gpw,
               float* __restrict__ out) {
    extern __shared__ float sm[];
    float* sBlob = sm + OFF_BLOB;
    float* sQ    = sm + OFF_Q;

    const int tid  = threadIdx.x;
    const int lane = tid & 31;
    const int wid  = tid >> 5;
    const int q0   = blockIdx.x * QT;

    const int wq = wid >> 2;      // 0..1
    const int wc = wid & 3;       // 0..3
    const int tr = lane >> 2;     // 0..7
    const int tc = lane & 3;      // 0..3

    const uint32_t smemBase = (uint32_t)__cvta_generic_to_shared(sm);
    const uint32_t mb_full  = smemBase + OFF_MBAR * 4;        // 3 x 8B
    const uint32_t mb_empty = mb_full + 24;                   // 3 x 8B
    const uint32_t sblobA   = smemBase + OFF_BLOB * 4;

    // ldmatrix lane offsets within a blob (mu section starts at CT floats)
    const uint32_t boff0 = (uint32_t)(CT * 4) +
        (uint32_t)(((32 * wc + ((lane >> 4) & 1) * 8 + (lane & 7)) * MUS
                    + ((lane >> 3) & 1) * 4) * 4);
    const uint32_t boff1 = boff0 + (uint32_t)(16 * MUS * 4);

    // hm2 quad word offsets (permuted+swizzled, from R10 - validated)
    const int blk0 = 2 * tc, blk1 = 2 * tc + 1;
    const int w0 = (blk0 * 16 + 4 * wc) ^ (blk0 << 2);
    const int w1 = (blk1 * 16 + 4 * wc) ^ (blk1 << 2);

    // ---- prologue ----
    if (tid == 0) {
#pragma unroll
        for (int b = 0; b < 3; b++) {
            mbar_init(mb_full + b * 8, 1);
            mbar_init(mb_empty + b * 8, 8);
        }
    }
    for (int idx = tid; idx < QT * DK; idx += 256) {
        int q = idx >> 6, k = idx & 63;
        sQ[q * MUS + k] = q_tilde[(size_t)(q0 + q) * DK + k];
    }
    __syncthreads();   // barriers + sQ visible
    if (tid == 0) {    // chunks 0,1 into buffers 0,1
        mbar_expect_tx(mb_full, BUFBYTES);
        bulk_g2s(sblobA, g_blob, BUFBYTES, mb_full);
        mbar_expect_tx(mb_full + 8, BUFBYTES);
        bulk_g2s(sblobA + BUFBYTES, g_blob + BUFFLOATS, BUFBYTES, mb_full + 8);
    }

    uint32_t af[8][4];
    {
        const float* qa = sQ + (16 * wq + tr) * MUS + tc;
#pragma unroll
        for (int kt = 0; kt < 8; kt++) {
            af[kt][0] = to_tf32(qa[8 * kt]);
            af[kt][1] = to_tf32(qa[8 * MUS + 8 * kt]);
            af[kt][2] = to_tf32(qa[8 * kt + 4]);
            af[kt][3] = to_tf32(qa[8 * MUS + 8 * kt + 4]);
        }
    }
    __syncthreads();   // all frag reads done -> buffer 2 may be overwritten

    // selection state: slots for 16 queries (lane = one of 32 slots each);
    // thresholds only for this lane's own two queries (rows tr, tr+8)
    unsigned cu[16]; int ci[16];
    const unsigned NEGINF_U = fenc(-INFINITY);
#pragma unroll
    for (int r = 0; r < 16; r++) { cu[r] = NEGINF_U; ci[r] = 0; }
    float thr_lo = -INFINITY, thr_hi = -INFINITY;

    for (int ch = 0; ch < NCHUNK; ++ch) {
        const int buf = ch % 3;
        mbar_wait(mb_full + buf * 8, (ch / 3) & 1);

        const uint32_t bufB = sblobA + (uint32_t)buf * BUFBYTES;
        const float*   hbp  = sBlob + buf * BUFFLOATS;

        // ---- GEMM: 16q x 32c ----
        float acc[4][4];
#pragma unroll
        for (int nt = 0; nt < 4; nt++)
#pragma unroll
            for (int j = 0; j < 4; j++) acc[nt][j] = 0.f;

        const uint32_t a0 = bufB + boff0;
        const uint32_t a1 = bufB + boff1;
#pragma unroll
        for (int kt = 0; kt < 8; kt++) {
            uint32_t r0, r1, r2, r3, s0, s1, s2, s3;
            ldsm_x4(a0 + kt * 32, r0, r1, r2, r3);
            ldsm_x4(a1 + kt * 32, s0, s1, s2, s3);
            mma_tf32(acc[0], af[kt], r0, r1);
            mma_tf32(acc[1], af[kt], r2, r3);
            mma_tf32(acc[2], af[kt], s0, s1);
            mma_tf32(acc[3], af[kt], s2, s3);
        }
        // hm2 loads from this buffer, then release it
        float4 h0 = *reinterpret_cast<const float4*>(hbp + w0);
        float4 h1 = *reinterpret_cast<const float4*>(hbp + w1);
        if (lane == 0) mbar_arrive(mb_empty + buf * 8);

        // producer: issue chunk ch+2 into buffer (ch+2)%3
        if (tid == 0 && ch + 2 < NCHUNK) {
            int c = ch + 2, b = c % 3;
            if (c >= 3) mbar_wait(mb_empty + b * 8, ((c / 3) - 1) & 1);
            mbar_expect_tx(mb_full + b * 8, BUFBYTES);
            bulk_g2s(sblobA + (uint32_t)b * BUFBYTES,
                     g_blob + (size_t)c * BUFFLOATS, BUFBYTES, mb_full + b * 8);
        }

        // ---- scores in place: acc[nt][{0,1}] rows tr, [{2,3}] rows tr+8 ----
        float ha[4] = {h0.x, h0.y, h0.z, h0.w};
        float hb2[4] = {h1.x, h1.y, h1.z, h1.w};
#pragma unroll
        for (int nt = 0; nt < 4; nt++) {
            acc[nt][0] -= ha[nt];  acc[nt][1] -= hb2[nt];
            acc[nt][2] -= ha[nt];  acc[nt][3] -= hb2[nt];
        }
        float vml = acc[0][0], vmh = acc[0][2];
#pragma unroll
        for (int nt = 0; nt < 4; nt++) {
            vml = fmaxf(vml, fmaxf(acc[nt][0], acc[nt][1]));
            vmh = fmaxf(vmh, fmaxf(acc[nt][2], acc[nt][3]));
        }

        // ---- streaming top-32 of this warp's slice ----
        if (__ballot_sync(FULLMASK, (vml > thr_lo) | (vmh > thr_hi))) {
            const int base = ch * CT + 32 * wc;
#pragma unroll
            for (int r = 0; r < 16; ++r) {
                const bool rsel = (r >= 8);
                const bool own  = (tr == (r & 7));
                float vm = rsel ? vmh : vml;
                float myth = rsel ? thr_hi : thr_lo;
                unsigned m = __ballot_sync(FULLMASK, own && (vm > myth));
                if (!m) continue;
                // lane-local argmax for owners
                int jmax = 0;
                {
                    float best = ROW_GET(rsel, 0);
#pragma unroll
                    for (int j = 1; j < 8; j++) {
                        float v = ROW_GET(rsel, j);
                        if (v > best) { best = v; jmax = j; }
                    }
                    vm = best;
                }
                while (m) {
                    int src = __ffs(m) - 1;
                    float nv = __shfl_sync(FULLMASK, vm, src);
                    int  jj  = __shfl_sync(FULLMASK, jmax, src);
                    unsigned umin = redux_min_u32(cu[r]);
                    unsigned bl = __ballot_sync(FULLMASK, cu[r] == umin);
                    int ml = __ffs(bl) - 1;
                    if (lane == ml) {
                        cu[r] = fenc(nv);
                        ci[r] = base + 8 * (jj >> 1) + 2 * (src & 3) + (jj & 1);
                    }
                    float nthr = fdec(redux_min_u32(cu[r]));
                    if (own) { if (rsel) thr_hi = nthr; else thr_lo = nthr; }
                    if (lane == src) {
#pragma unroll
                        for (int j = 0; j < 8; j++)
                            if (j == jj) ROW_SET(rsel, j, -INFINITY);
                        vm = -INFINITY; jmax = 0;
#pragma unroll
                        for (int j = 0; j < 8; j++) {
                            float v = ROW_GET(rsel, j);
                            if (v > vm) { vm = v; jmax = j; }
                        }
                    }
                    m = __ballot_sync(FULLMASK, own && (vm > nthr));
                }
            }
        }
    }

    __syncthreads();   // all warps done with loop; blob area now reusable

    // ---- publish per-slice top-32 lists ----
    float* sMV = sm + OFF_MV;
    int*   sMI = reinterpret_cast<int*>(sm + OFF_MI);
#pragma unroll
    for (int r = 0; r < 16; r++) {
        int q = 16 * wq + r;
        sMV[q * 128 + 32 * wc + lane] = fdec(cu[r]);
        sMI[q * 128 + 32 * wc + lane] = ci[r];
    }
    __syncthreads();

    // ---- merge 4 slices -> global top-32 per query ----
    int* sTopI = reinterpret_cast<int*>(sm + OFF_TI);
#pragma unroll
    for (int round = 0; round < 4; ++round) {
        int q = wid + 8 * round;
        float v[4]; int id[4];
#pragma unroll
        for (int s = 0; s < 4; s++) {
            v[s]  = sMV[q * 128 + 32 * s + lane];
            id[s] = sMI[q * 128 + 32 * s + lane];
        }
        unsigned mcu = NEGINF_U; int mci = 0; float mthr = -INFINITY;
#pragma unroll
        for (int s = 0; s < 4; s++) {
            unsigned m = __ballot_sync(FULLMASK, v[s] > mthr);
            while (m) {
                int src = __ffs(m) - 1;
                m &= m - 1;
                float nv = __shfl_sync(FULLMASK, v[s], src);
                int  ni  = __shfl_sync(FULLMASK, id[s], src);
                if (nv > mthr) {
                    unsigned umin = redux_min_u32(mcu);
                    unsigned bl = __ballot_sync(FULLMASK, mcu == umin);
                    int ml = __ffs(bl) - 1;
                    if (lane == ml) { mcu = fenc(nv); mci = ni; }
                    mthr = fdec(redux_min_u32(mcu));
                }
            }
        }
        sTopI[q * 32 + lane] = mci;
    }
    __syncthreads();

    const float sigma  = sig[0];
    const float inv_s2 = 1.f / (sigma * sigma);
    const float bgate  = Wgb[0];
    const float gw     = gpw[0];

    float* myW = sm + OFF_SCR + wid * 64;
    int*   myI = reinterpret_cast<int*>(myW + 32);

    // ---- epilogue: EXACT rescore + softmax + gathers + gate ----
#pragma unroll
    for (int round = 0; round < 4; ++round) {
        int q   = wid + 8 * round;
        int qg2 = q0 + q;

        int idx = sTopI[q * 32 + lane];

        const float4* mrow = reinterpret_cast<const float4*>(mu + (size_t)idx * DK);
        const float4* qrow = reinterpret_cast<const float4*>(q_tilde + (size_t)qg2 * DK);
        float d0 = 0.f, d1 = 0.f, d2 = 0.f, d3 = 0.f;
#pragma unroll
        for (int j = 0; j < 16; j += 4) {
            float4 m0 = mrow[j],     qv0 = qrow[j];
            float4 m1 = mrow[j + 1], qv1 = qrow[j + 1];
            float4 m2 = mrow[j + 2], qv2 = qrow[j + 2];
            float4 m3 = mrow[j + 3], qv3 = qrow[j + 3];
            d0 += m0.x * qv0.x + m0.y * qv0.y + m0.z * qv0.z + m0.w * qv0.w;
            d1 += m1.x * qv1.x + m1.y * qv1.y + m1.z * qv1.z + m1.w * qv1.w;
            d2 += m2.x * qv2.x + m2.y * qv2.y + m2.z * qv2.z + m2.w * qv2.w;
            d3 += m3.x * qv3.x + m3.y * qv3.y + m3.z * qv3.z + m3.w * qv3.w;
        }
        float s = ((d0 + d1) + (d2 + d3) - g_hm2[idx]) * inv_s2;

        float mx = s;
#pragma unroll
        for (int off = 16; off; off >>= 1)
            mx = fmaxf(mx, __shfl_xor_sync(FULLMASK, mx, off));
        float e = __expf(s - mx);
        float se = e;
#pragma unroll
        for (int off = 16; off; off >>= 1)
            se += __shfl_xor_sync(FULLMASK, se, off);
        float wgt = e / se;

        myW[lane] = wgt;
        myI[lane] = idx;
        __syncwarp();

        float4 acc = make_float4(0.f, 0.f, 0.f, 0.f);
#pragma unroll 4
        for (int k = 0; k < 32; k++) {
            float wk = myW[k];
            size_t row = (size_t)myI[k];
            float4 v = reinterpret_cast<const float4*>(V + row * 128)[lane];
            acc.x += wk * v.x; acc.y += wk * v.y;
            acc.z += wk * v.z; acc.w += wk * v.w;
        }

        float re = 0.f;
        if (lane < 4) {
            for (int k = 0; k < 32; k++)
                re += myW[k] * E[(size_t)myI[k] * 4 + lane];
        }

        const float4 wv = reinterpret_cast<const float4*>(Wg + 256)[lane];
        float tot = acc.x * wv.x + acc.y * wv.y + acc.z * wv.z + acc.w * wv.w;
        const float* xq = x + (size_t)qg2 * 256;
#pragma unroll
        for (int u = 0; u < 8; u++) {
            int t = lane + 32 * u;
            tot += xq[t] * Wg[t];
        }
#pragma unroll
        for (int off = 16; off; off >>= 1)
            tot += __shfl_xor_sync(FULLMASK, tot, off);

        reinterpret_cast<float4*>(out + RV_OFF + (size_t)qg2 * 128)[lane] = acc;
        if (lane < 4) out[RE_OFF + (size_t)qg2 * 4 + lane] = re;
        if (lane == 0) {
            float z = tot + bgate + gw * g_prior[qg2];
            out[G_OFF + qg2] = 1.f / (1.f + __expf(-z));
        }
        __syncwarp();
    }
}

extern "C" void kernel_launch(void* const* d_in, const int* in_sizes, int n_in,
                              void* d_out, int out_size) {
    (void)in_sizes; (void)n_in; (void)out_size;
    const float* x   = (const float*)d_in[0];
    const float* qt  = (const float*)d_in[1];
    const float* gp  = (const float*)d_in[2];
    const float* mu  = (const float*)d_in[3];
    const float* V   = (const float*)d_in[4];
    const float* E   = (const float*)d_in[5];
    const float* sg  = (const float*)d_in[6];
    const float* Wg  = (const float*)d_in[7];
    const float* Wb  = (const float*)d_in[8];
    const float* gw  = (const float*)d_in[9];

    prep_kernel<<<NC / 256, 256>>>(mu);

    const int smem_bytes = SMEM_FLOATS * 4;   // 106048
    cudaFuncSetAttribute(ma_kernel, cudaFuncAttributeMaxDynamicSharedMemorySize,
                         smem_bytes);
    ma_kernel<<<NQ / QT, 256, smem_bytes>>>(x, qt, gp, mu, V, E, sg, Wg, Wb, gw,
                                            (float*)d_out);
}

// round 13
// speedup vs baseline: 2.9901x; 2.9901x over previous
#include <cuda_runtime.h>
#include <cstdint>

// ---------------------------------------------------------------------------
// MemoryAttention R13: R10 dataflow, mbarrier-decoupled (no in-loop CTA sync).
//   - All 8 warps do GEMM (tf32 mma + ldmatrix) AND selection, as R10.
//   - Per-chunk __syncthreads replaced by 4 mbarrier families (2 bufs each):
//       mu_full  (TMA tx)            : wait before GEMM(ch)
//       mu_empty (8 warp arrivals)   : producer waits before TMA(ch) reuse
//       sc_full  (8 warp arrivals)   : wait before select(ch)
//       sc_empty (8 warp arrivals)   : wait before score stores reuse buffer
//     Warps proceed independently with 1-chunk slack; straggler insert bursts
//     no longer stall the whole CTA.
//   - Everything else identical to R10 (TMA blob, permuted+swizzled scores,
//     streaming top-32, exact fp32 rescore epilogue).
// ---------------------------------------------------------------------------

#define FULLMASK 0xffffffffu

constexpr int NQ  = 8192;
constexpr int NC  = 32768;
constexpr int DK  = 64;
constexpr int QT  = 32;        // queries per CTA
constexpr int CT  = 128;       // centers per chunk
constexpr int NCHUNK = NC / CT;    // 256
constexpr int MUS  = 68;       // mu row stride (floats) inside blob
constexpr int SSTR = 132;      // score row stride
constexpr int SBUF = QT * SSTR;    // floats per score buffer
constexpr int BUFFLOATS = CT + CT * MUS;      // 128 hm2 + 8704 mu = 8832
constexpr uint32_t BUFBYTES = BUFFLOATS * 4;  // 35328 B

static __device__ float g_hm2[NC];
static __device__ float g_blob[(size_t)NCHUNK * BUFFLOATS];   // ~9 MB

constexpr int RV_OFF = 0;
constexpr int RE_OFF = NQ * 128;
constexpr int G_OFF  = RE_OFF + NQ * 4;

// smem layout (floats)
constexpr int OFF_MBAR = 0;                        // 8 mbarriers = 64 B
constexpr int OFF_BLOB = 16;                       // 2*8832 = 17664
constexpr int OFF_S0   = OFF_BLOB + 2 * BUFFLOATS; // 4224 (sQ aliases here)
constexpr int OFF_S1   = OFF_S0 + SBUF;            // 4224
constexpr int OFF_SCR  = OFF_S1 + SBUF;            // 512
constexpr int SMEM_FLOATS = OFF_SCR + 8 * 64;      // 26640 f = 106560 B

__device__ __forceinline__ uint32_t to_tf32(float f) {
    uint32_t u;
    asm("cvt.rna.tf32.f32 %0, %1;" : "=r"(u) : "f"(f));
    return u;
}

__global__ void prep_kernel(const float* __restrict__ mu) {
    int c = blockIdx.x * 256 + threadIdx.x;   // 32768 rows
    const float4* r = reinterpret_cast<const float4*>(mu) + (size_t)c * 16;
    int n = c & 127;
    float* blob = g_blob + (size_t)(c >> 7) * BUFFLOATS;
    float4* w = reinterpret_cast<float4*>(blob + CT + n * MUS);
    float s = 0.f;
#pragma unroll
    for (int j = 0; j < 16; j++) {
        float4 v = r[j];
        s += v.x * v.x + v.y * v.y + v.z * v.z + v.w * v.w;
        float4 t;
        t.x = __uint_as_float(to_tf32(v.x));
        t.y = __uint_as_float(to_tf32(v.y));
        t.z = __uint_as_float(to_tf32(v.z));
        t.w = __uint_as_float(to_tf32(v.w));
        w[j] = t;
    }
    int p  = (n & 7) * 16 + (n >> 3);
    int ws = p ^ (((p >> 4) & 7) << 2);
    blob[ws] = 0.5f * s;
    g_hm2[c] = 0.5f * s;
}

__device__ __forceinline__ unsigned fenc(float f) {
    unsigned u = __float_as_uint(f);
    return (u & 0x80000000u) ? ~u : (u | 0x80000000u);
}
__device__ __forceinline__ float fdec(unsigned u) {
    return (u & 0x80000000u) ? __uint_as_float(u & 0x7fffffffu)
                             : __uint_as_float(~u);
}
__device__ __forceinline__ unsigned redux_min_u32(unsigned v) {
    unsigned r;
    asm("redux.sync.min.u32 %0, %1, 0xffffffff;" : "=r"(r) : "r"(v));
    return r;
}
__device__ __forceinline__ void mma_tf32(float* d, const uint32_t* a,
                                         uint32_t b0, uint32_t b1) {
    asm("mma.sync.aligned.m16n8k8.row.col.f32.tf32.tf32.f32 "
        "{%0,%1,%2,%3}, {%4,%5,%6,%7}, {%8,%9}, {%0,%1,%2,%3};"
        : "+f"(d[0]), "+f"(d[1]), "+f"(d[2]), "+f"(d[3])
        : "r"(a[0]), "r"(a[1]), "r"(a[2]), "r"(a[3]), "r"(b0), "r"(b1));
}
__device__ __forceinline__ void ldsm_x4(uint32_t addr, uint32_t& r0,
                                        uint32_t& r1, uint32_t& r2, uint32_t& r3) {
    asm volatile("ldmatrix.sync.aligned.m8n8.x4.shared.b16 {%0,%1,%2,%3}, [%4];"
                 : "=r"(r0), "=r"(r1), "=r"(r2), "=r"(r3) : "r"(addr));
}
__device__ __forceinline__ void mbar_init(uint32_t addr, uint32_t count) {
    asm volatile("mbarrier.init.shared.b64 [%0], %1;" :: "r"(addr), "r"(count)
                 : "memory");
}
__device__ __forceinline__ void mbar_arrive(uint32_t addr) {
    asm volatile("mbarrier.arrive.release.cta.shared.b64 _, [%0];"
                 :: "r"(addr) : "memory");
}
__device__ __forceinline__ void mbar_expect_tx(uint32_t addr, uint32_t bytes) {
    asm volatile("mbarrier.arrive.expect_tx.shared.b64 _, [%0], %1;"
                 :: "r"(addr), "r"(bytes) : "memory");
}
__device__ __forceinline__ void mbar_wait(uint32_t addr, uint32_t parity) {
    asm volatile(
        "{\n\t"
        ".reg .pred P;\n"
        "W_%=:\n\t"
        "mbarrier.try_wait.parity.acquire.cta.shared::cta.b64 P, [%0], %1, 0x989680;\n\t"
        "@P bra D_%=;\n\t"
        "bra W_%=;\n"
        "D_%=:\n\t"
        "}"
        :: "r"(addr), "r"(parity) : "memory");
}
__device__ __forceinline__ void bulk_g2s(uint32_t dst, const void* src,
                                         uint32_t bytes, uint32_t mbar) {
    asm volatile(
        "cp.async.bulk.shared::cta.global.mbarrier::complete_tx::bytes "
        "[%0], [%1], %2, [%3];"
        :: "r"(dst), "l"(src), "r"(bytes), "r"(mbar) : "memory");
}

__global__ __launch_bounds__(256, 2)
void ma_kernel(const float* __restrict__ x,
               const float* __restrict__ q_tilde,
               const float* __restrict__ g_prior,
               const float* __restrict__ mu,
               const float* __restrict__ V,
               const float* __restrict__ E,
               const float* __restrict__ sig,
               const float* __restrict__ Wg,
               const float* __restrict__ Wgb,
               const float* __restrict__ gpw,
               float* __restrict__ out) {
    extern __shared__ float sm[];
    float* sBlob = sm + OFF_BLOB;
    float* sS    = sm + OFF_S0;     // two score buffers
    float* sQ    = sm + OFF_S0;     // alias: Q staged here only for A-frags
    float* sScr  = sm + OFF_SCR;

    const int tid  = threadIdx.x;
    const int lane = tid & 31;
    const int wid  = tid >> 5;
    const int q0   = blockIdx.x * QT;

    const int wq = wid >> 2;      // 0..1
    const int wc = wid & 3;       // 0..3
    const int tr = lane >> 2;     // 0..7
    const int tc = lane & 3;      // 0..3

    const uint32_t smemBase = (uint32_t)__cvta_generic_to_shared(sm);
    const uint32_t mb_mu_full  = smemBase + OFF_MBAR * 4;   // +0, +8
    const uint32_t mb_mu_empty = mb_mu_full + 16;           // +16,+24
    const uint32_t mb_sc_full  = mb_mu_full + 32;           // +32,+40
    const uint32_t mb_sc_empty = mb_mu_full + 48;           // +48,+56
    const uint32_t sblobA = smemBase + OFF_BLOB * 4;

    // ldmatrix lane offsets within a blob (mu section starts at CT floats)
    const uint32_t boff0 = (uint32_t)(CT * 4) +
        (uint32_t)(((32 * wc + ((lane >> 4) & 1) * 8 + (lane & 7)) * MUS
                    + ((lane >> 3) & 1) * 4) * 4);
    const uint32_t boff1 = boff0 + (uint32_t)(16 * MUS * 4);

    // swizzled word offsets for this thread's hm2 / score float4s (R10)
    const int blk0 = 2 * tc, blk1 = 2 * tc + 1;
    const int w0 = (blk0 * 16 + 4 * wc) ^ (blk0 << 2);
    const int w1 = (blk1 * 16 + 4 * wc) ^ (blk1 << 2);

    // ---- prologue ----
    if (tid == 0) {
        mbar_init(mb_mu_full, 1);      mbar_init(mb_mu_full + 8, 1);
        mbar_init(mb_mu_empty, 8);     mbar_init(mb_mu_empty + 8, 8);
        mbar_init(mb_sc_full, 8);      mbar_init(mb_sc_full + 8, 8);
        mbar_init(mb_sc_empty, 8);     mbar_init(mb_sc_empty + 8, 8);
    }
    for (int idx = tid; idx < QT * DK; idx += 256) {
        int q = idx >> 6, k = idx & 63;
        sQ[q * MUS + k] = q_tilde[(size_t)(q0 + q) * DK + k];
    }
    __syncthreads();    // barriers + sQ visible
    if (tid == 0) {     // chunk 0
        mbar_expect_tx(mb_mu_full, BUFBYTES);
        bulk_g2s(sblobA, g_blob, BUFBYTES, mb_mu_full);
    }

    uint32_t af[8][4];
    {
        const float* qa = sQ + (16 * wq + tr) * MUS + tc;
#pragma unroll
        for (int kt = 0; kt < 8; kt++) {
            af[kt][0] = to_tf32(qa[8 * kt]);
            af[kt][1] = to_tf32(qa[8 * MUS + 8 * kt]);
            af[kt][2] = to_tf32(qa[8 * kt + 4]);
            af[kt][3] = to_tf32(qa[8 * MUS + 8 * kt + 4]);
        }
    }
    __syncthreads();    // all frag reads done before scores(0) land in sS0

    // selection state: warp wid owns queries 4*wid + r
    unsigned cu[4]; int ci[4]; float thr[4]; unsigned thrU[4];
    const unsigned NEGINF_U = fenc(-INFINITY);
#pragma unroll
    for (int r = 0; r < 4; r++) {
        cu[r] = NEGINF_U; ci[r] = 0; thr[r] = -INFINITY; thrU[r] = NEGINF_U;
    }

    const int selw = 4 * (lane ^ (lane >> 2));   // swizzled select load offset

    auto select_chunk = [&](const float* sbuf, int base) {
        float4 f[4]; float lmax[4];
#pragma unroll
        for (int r = 0; r < 4; r++) {
            const float* row = sbuf + (4 * wid + r) * SSTR;
            f[r] = *reinterpret_cast<const float4*>(row + selw);
            lmax[r] = fmaxf(fmaxf(f[r].x, f[r].y), fmaxf(f[r].z, f[r].w));
        }
        bool anyc = (lmax[0] > thr[0]) | (lmax[1] > thr[1]) |
                    (lmax[2] > thr[2]) | (lmax[3] > thr[3]);
        if (!__ballot_sync(FULLMASK, anyc)) return;
#pragma unroll
        for (int r = 0; r < 4; r++) {
            unsigned m = __ballot_sync(FULLMASK, lmax[r] > thr[r]);
            while (m) {
                int src = __ffs(m) - 1;
                m &= m - 1;
                float g0 = __shfl_sync(FULLMASK, f[r].x, src);
                float g1 = __shfl_sync(FULLMASK, f[r].y, src);
                float g2 = __shfl_sync(FULLMASK, f[r].z, src);
                float g3 = __shfl_sync(FULLMASK, f[r].w, src);
                int ib = base + 32 * (src & 3) + (src >> 2);
#pragma unroll
                for (int j = 0; j < 4; j++) {
                    float nv = (j == 0) ? g0 : (j == 1) ? g1 : (j == 2) ? g2 : g3;
                    if (nv > thr[r]) {
                        unsigned bl = __ballot_sync(FULLMASK, cu[r] == thrU[r]);
                        int ml = __ffs(bl) - 1;
                        if (lane == ml) { cu[r] = fenc(nv); ci[r] = ib + 8 * j; }
                        thrU[r] = redux_min_u32(cu[r]);
                        thr[r]  = fdec(thrU[r]);
                    }
                }
            }
        }
    };

    for (int ch = 0; ch < NCHUNK; ++ch) {
        const int buf = ch & 1;
        mbar_wait(mb_mu_full + buf * 8, (ch >> 1) & 1);

        const uint32_t bufB = sblobA + (uint32_t)buf * BUFBYTES;
        const float*   hbp  = sBlob + buf * BUFFLOATS;

        // ---- tensor-core GEMM: warp tile 16q x 32c ----
        float acc[4][4];
#pragma unroll
        for (int nt = 0; nt < 4; nt++)
#pragma unroll
            for (int j = 0; j < 4; j++) acc[nt][j] = 0.f;

        const uint32_t a0 = bufB + boff0;
        const uint32_t a1 = bufB + boff1;
#pragma unroll
        for (int kt = 0; kt < 8; kt++) {
            uint32_t r0, r1, r2, r3, s0, s1, s2, s3;
            ldsm_x4(a0 + kt * 32, r0, r1, r2, r3);
            ldsm_x4(a1 + kt * 32, s0, s1, s2, s3);
            mma_tf32(acc[0], af[kt], r0, r1);
            mma_tf32(acc[1], af[kt], r2, r3);
            mma_tf32(acc[2], af[kt], s0, s1);
            mma_tf32(acc[3], af[kt], s2, s3);
        }

        // hm2 loads + fold into scores (consumes the buffer), then release it
        float4 h0 = *reinterpret_cast<const float4*>(hbp + w0);
        float4 h1 = *reinterpret_cast<const float4*>(hbp + w1);
        float4 v0, v1, v2, v3;
        v0.x = acc[0][0] - h0.x; v0.y = acc[1][0] - h0.y;
        v0.z = acc[2][0] - h0.z; v0.w = acc[3][0] - h0.w;
        v1.x = acc[0][1] - h1.x; v1.y = acc[1][1] - h1.y;
        v1.z = acc[2][1] - h1.z; v1.w = acc[3][1] - h1.w;
        v2.x = acc[0][2] - h0.x; v2.y = acc[1][2] - h0.y;
        v2.z = acc[2][2] - h0.z; v2.w = acc[3][2] - h0.w;
        v3.x = acc[0][3] - h1.x; v3.y = acc[1][3] - h1.y;
        v3.z = acc[2][3] - h1.z; v3.w = acc[3][3] - h1.w;
        __syncwarp();
        if (lane == 0) mbar_arrive(mb_mu_empty + buf * 8);

        // producer: issue TMA for chunk ch+1
        if (tid == 0 && ch + 1 < NCHUNK) {
            int c = ch + 1, b = c & 1;
            if (c >= 2) mbar_wait(mb_mu_empty + b * 8, ((c >> 1) - 1) & 1);
            mbar_expect_tx(mb_mu_full + b * 8, BUFBYTES);
            bulk_g2s(sblobA + (uint32_t)b * BUFBYTES,
                     g_blob + (size_t)c * BUFFLOATS, BUFBYTES, mb_mu_full + b * 8);
        }

        // ---- deferred selection of chunk ch-1 ----
        if (ch > 0) {
            const int pb = (ch - 1) & 1;
            mbar_wait(mb_sc_full + pb * 8, ((ch - 1) >> 1) & 1);
            select_chunk(sS + pb * SBUF, (ch - 1) * CT);
            __syncwarp();
            if (lane == 0) mbar_arrive(mb_sc_empty + pb * 8);
        }

        // ---- store scores(ch) into buffer ch&1 ----
        if (ch >= 2) mbar_wait(mb_sc_empty + buf * 8, ((ch >> 1) - 1) & 1);
        {
            float* sb = sS + buf * SBUF;
            float* r0p = sb + (16 * wq + tr) * SSTR;
            float* r1p = r0p + 8 * SSTR;
            *reinterpret_cast<float4*>(r0p + w0) = v0;
            *reinterpret_cast<float4*>(r0p + w1) = v1;
            *reinterpret_cast<float4*>(r1p + w0) = v2;
            *reinterpret_cast<float4*>(r1p + w1) = v3;
        }
        __syncwarp();
        if (lane == 0) mbar_arrive(mb_sc_full + buf * 8);
    }

    // final chunk's selection
    {
        const int pb = (NCHUNK - 1) & 1;
        mbar_wait(mb_sc_full + pb * 8, ((NCHUNK - 1) >> 1) & 1);
        select_chunk(sS + pb * SBUF, (NCHUNK - 1) * CT);
    }
    __syncthreads();   // all selects done; score buffers reusable

    // publish top-32 indices per query into sS0
    int* sTopI = reinterpret_cast<int*>(sS);
#pragma unroll
    for (int r = 0; r < 4; r++) {
        int q = 4 * wid + r;
        sTopI[q * 32 + lane] = ci[r];
    }
    __syncthreads();

    const float sigma  = sig[0];
    const float inv_s2 = 1.f / (sigma * sigma);
    const float bgate  = Wgb[0];
    const float gw     = gpw[0];

    float* myW = sScr + wid * 64;
    int*   myI = reinterpret_cast<int*>(myW + 32);

    // ---- epilogue: EXACT rescore + softmax + gathers + gate ----
#pragma unroll
    for (int round = 0; round < 4; ++round) {
        int q   = wid + 8 * round;
        int qg2 = q0 + q;

        int idx = sTopI[q * 32 + lane];

        const float4* mrow = reinterpret_cast<const float4*>(mu + (size_t)idx * DK);
        const float4* qrow = reinterpret_cast<const float4*>(q_tilde + (size_t)qg2 * DK);
        float d0 = 0.f, d1 = 0.f, d2 = 0.f, d3 = 0.f;
#pragma unroll
        for (int j = 0; j < 16; j += 4) {
            float4 m0 = mrow[j],     qv0 = qrow[j];
            float4 m1 = mrow[j + 1], qv1 = qrow[j + 1];
            float4 m2 = mrow[j + 2], qv2 = qrow[j + 2];
            float4 m3 = mrow[j + 3], qv3 = qrow[j + 3];
            d0 += m0.x * qv0.x + m0.y * qv0.y + m0.z * qv0.z + m0.w * qv0.w;
            d1 += m1.x * qv1.x + m1.y * qv1.y + m1.z * qv1.z + m1.w * qv1.w;
            d2 += m2.x * qv2.x + m2.y * qv2.y + m2.z * qv2.z + m2.w * qv2.w;
            d3 += m3.x * qv3.x + m3.y * qv3.y + m3.z * qv3.z + m3.w * qv3.w;
        }
        float s = ((d0 + d1) + (d2 + d3) - g_hm2[idx]) * inv_s2;

        float mx = s;
#pragma unroll
        for (int off = 16; off; off >>= 1)
            mx = fmaxf(mx, __shfl_xor_sync(FULLMASK, mx, off));
        float e = __expf(s - mx);
        float se = e;
#pragma unroll
        for (int off = 16; off; off >>= 1)
            se += __shfl_xor_sync(FULLMASK, se, off);
        float wgt = e / se;

        myW[lane] = wgt;
        myI[lane] = idx;
        __syncwarp();

        float4 acc = make_float4(0.f, 0.f, 0.f, 0.f);
#pragma unroll 4
        for (int k = 0; k < 32; k++) {
            float wk = myW[k];
            size_t row = (size_t)myI[k];
            float4 v = reinterpret_cast<const float4*>(V + row * 128)[lane];
            acc.x += wk * v.x; acc.y += wk * v.y;
            acc.z += wk * v.z; acc.w += wk * v.w;
        }

        float re = 0.f;
        if (lane < 4) {
            for (int k = 0; k < 32; k++)
                re += myW[k] * E[(size_t)myI[k] * 4 + lane];
        }

        const float4 wv = reinterpret_cast<const float4*>(Wg + 256)[lane];
        float tot = acc.x * wv.x + acc.y * wv.y + acc.z * wv.z + acc.w * wv.w;
        const float* xq = x + (size_t)qg2 * 256;
#pragma unroll
        for (int u = 0; u < 8; u++) {
            int t = lane + 32 * u;
            tot += xq[t] * Wg[t];
        }
#pragma unroll
        for (int off = 16; off; off >>= 1)
            tot += __shfl_xor_sync(FULLMASK, tot, off);

        reinterpret_cast<float4*>(out + RV_OFF + (size_t)qg2 * 128)[lane] = acc;
        if (lane < 4) out[RE_OFF + (size_t)qg2 * 4 + lane] = re;
        if (lane == 0) {
            float z = tot + bgate + gw * g_prior[qg2];
            out[G_OFF + qg2] = 1.f / (1.f + __expf(-z));
        }
        __syncwarp();
    }
}

extern "C" void kernel_launch(void* const* d_in, const int* in_sizes, int n_in,
                              void* d_out, int out_size) {
    (void)in_sizes; (void)n_in; (void)out_size;
    const float* x   = (const float*)d_in[0];
    const float* qt  = (const float*)d_in[1];
    const float* gp  = (const float*)d_in[2];
    const float* mu  = (const float*)d_in[3];
    const float* V   = (const float*)d_in[4];
    const float* E   = (const float*)d_in[5];
    const float* sg  = (const float*)d_in[6];
    const float* Wg  = (const float*)d_in[7];
    const float* Wb  = (const float*)d_in[8];
    const float* gw  = (const float*)d_in[9];

    prep_kernel<<<NC / 256, 256>>>(mu);

    const int smem_bytes = SMEM_FLOATS * 4;   // 106560
    cudaFuncSetAttribute(ma_kernel, cudaFuncAttributeMaxDynamicSharedMemorySize,
                         smem_bytes);
    ma_kernel<<<NQ / QT, 256, smem_bytes>>>(x, qt, gp, mu, V, E, sg, Wg, Wb, gw,
                                            (float*)d_out);
}

// round 14
// speedup vs baseline: 3.3056x; 1.1055x over previous
#include <cuda_runtime.h>
#include <cstdint>

// ---------------------------------------------------------------------------
// MemoryAttention R14: R10 sync structure + deduplicated LDSM (32q x 16c tile).
//   - Each warp owns ALL 32 queries x 16 exclusive columns: one ldmatrix.x4
//     per k-tile feeds 4 MMAs (2 m-tiles x 2 n-tiles). LDSM/warp/chunk 16->8.
//   - hm2 as one LDS.128 per thread (quad layout written by prep kernel).
//   - score stores: row-shifted layout W=(16(w^(R&1))+4tc-4R) mod 128 ->
//     conflict-free stores AND swizzle-free select loads (float4 at 4*lane);
//     column decode only on rare inserts.
//   - TMA blob, mbar+one-barrier/chunk pipeline, deferred select, exact
//     fp32 rescore epilogue: identical to R10.
// ---------------------------------------------------------------------------

#define FULLMASK 0xffffffffu

constexpr int NQ  = 8192;
constexpr int NC  = 32768;
constexpr int DK  = 64;
constexpr int QT  = 32;        // queries per CTA
constexpr int CT  = 128;       // centers per chunk
constexpr int NCHUNK = NC / CT;    // 256
constexpr int MUS  = 68;       // mu row stride (floats) inside blob
constexpr int SSTR = 132;      // score row stride
constexpr int SBUF = QT * SSTR;    // floats per score buffer
constexpr int BUFFLOATS = CT + CT * MUS;      // 128 hm2 + 8704 mu = 8832
constexpr uint32_t BUFBYTES = BUFFLOATS * 4;  // 35328 B

static __device__ float g_hm2[NC];
static __device__ float g_blob[(size_t)NCHUNK * BUFFLOATS];   // ~9 MB

constexpr int RV_OFF = 0;
constexpr int RE_OFF = NQ * 128;
constexpr int G_OFF  = RE_OFF + NQ * 4;

// smem layout (floats)
constexpr int OFF_MBAR = 0;                        // 2 mbarriers
constexpr int OFF_BLOB = 16;                       // 2*8832 = 17664
constexpr int OFF_S0   = OFF_BLOB + 2 * BUFFLOATS; // 4224 (sQ aliases here)
constexpr int OFF_S1   = OFF_S0 + SBUF;            // 4224
constexpr int OFF_SCR  = OFF_S1 + SBUF;            // 512
constexpr int SMEM_FLOATS = OFF_SCR + 8 * 64;      // 26640 f = 106560 B

__device__ __forceinline__ uint32_t to_tf32(float f) {
    uint32_t u;
    asm("cvt.rna.tf32.f32 %0, %1;" : "=r"(u) : "f"(f));
    return u;
}

__global__ void prep_kernel(const float* __restrict__ mu) {
    int c = blockIdx.x * 256 + threadIdx.x;   // 32768 rows
    const float4* r = reinterpret_cast<const float4*>(mu) + (size_t)c * 16;
    int n = c & 127;
    float* blob = g_blob + (size_t)(c >> 7) * BUFFLOATS;
    float4* w4 = reinterpret_cast<float4*>(blob + CT + n * MUS);
    float s = 0.f;
#pragma unroll
    for (int j = 0; j < 16; j++) {
        float4 v = r[j];
        s += v.x * v.x + v.y * v.y + v.z * v.z + v.w * v.w;
        float4 t;
        t.x = __uint_as_float(to_tf32(v.x));
        t.y = __uint_as_float(to_tf32(v.y));
        t.z = __uint_as_float(to_tf32(v.z));
        t.w = __uint_as_float(to_tf32(v.w));
        w4[j] = t;
    }
    // hm2 quad layout: thread (w,tc) reads float4 =
    //   { hm2[16w+2tc], hm2[16w+2tc+1], hm2[16w+8+2tc], hm2[16w+8+2tc+1] }
    int w  = n >> 4, inner = n & 15;
    int h  = inner >> 3, rem = inner & 7;
    int tc = rem >> 1, e = rem & 1;
    blob[(w * 4 + tc) * 4 + 2 * h + e] = 0.5f * s;
    g_hm2[c] = 0.5f * s;
}

__device__ __forceinline__ unsigned fenc(float f) {
    unsigned u = __float_as_uint(f);
    return (u & 0x80000000u) ? ~u : (u | 0x80000000u);
}
__device__ __forceinline__ float fdec(unsigned u) {
    return (u & 0x80000000u) ? __uint_as_float(u & 0x7fffffffu)
                             : __uint_as_float(~u);
}
__device__ __forceinline__ unsigned redux_min_u32(unsigned v) {
    unsigned r;
    asm("redux.sync.min.u32 %0, %1, 0xffffffff;" : "=r"(r) : "r"(v));
    return r;
}
__device__ __forceinline__ void mma_tf32(float* d, const uint32_t* a,
                                         uint32_t b0, uint32_t b1) {
    asm("mma.sync.aligned.m16n8k8.row.col.f32.tf32.tf32.f32 "
        "{%0,%1,%2,%3}, {%4,%5,%6,%7}, {%8,%9}, {%0,%1,%2,%3};"
        : "+f"(d[0]), "+f"(d[1]), "+f"(d[2]), "+f"(d[3])
        : "r"(a[0]), "r"(a[1]), "r"(a[2]), "r"(a[3]), "r"(b0), "r"(b1));
}
__device__ __forceinline__ void ldsm_x4(uint32_t addr, uint32_t& r0,
                                        uint32_t& r1, uint32_t& r2, uint32_t& r3) {
    asm volatile("ldmatrix.sync.aligned.m8n8.x4.shared.b16 {%0,%1,%2,%3}, [%4];"
                 : "=r"(r0), "=r"(r1), "=r"(r2), "=r"(r3) : "r"(addr));
}
__device__ __forceinline__ void mbar_init(uint32_t addr, uint32_t count) {
    asm volatile("mbarrier.init.shared.b64 [%0], %1;" :: "r"(addr), "r"(count)
                 : "memory");
}
__device__ __forceinline__ void mbar_expect_tx(uint32_t addr, uint32_t bytes) {
    asm volatile("mbarrier.arrive.expect_tx.shared.b64 _, [%0], %1;"
                 :: "r"(addr), "r"(bytes) : "memory");
}
__device__ __forceinline__ void mbar_wait(uint32_t addr, uint32_t parity) {
    asm volatile(
        "{\n\t"
        ".reg .pred P;\n"
        "W_%=:\n\t"
        "mbarrier.try_wait.parity.acquire.cta.shared::cta.b64 P, [%0], %1, 0x989680;\n\t"
        "@P bra D_%=;\n\t"
        "bra W_%=;\n"
        "D_%=:\n\t"
        "}"
        :: "r"(addr), "r"(parity) : "memory");
}
__device__ __forceinline__ void bulk_g2s(uint32_t dst, const void* src,
                                         uint32_t bytes, uint32_t mbar) {
    asm volatile(
        "cp.async.bulk.shared::cta.global.mbarrier::complete_tx::bytes "
        "[%0], [%1], %2, [%3];"
        :: "r"(dst), "l"(src), "r"(bytes), "r"(mbar) : "memory");
}

__global__ __launch_bounds__(256, 2)
void ma_kernel(const float* __restrict__ x,
               const float* __restrict__ q_tilde,
               const float* __restrict__ g_prior,
               const float* __restrict__ mu,
               const float* __restrict__ V,
               const float* __restrict__ E,
               const float* __restrict__ sig,
               const float* __restrict__ Wg,
               const float* __restrict__ Wgb,
               const float* __restrict__ gpw,
               float* __restrict__ out) {
    extern __shared__ float sm[];
    float* sBlob = sm + OFF_BLOB;
    float* sS    = sm + OFF_S0;     // two score buffers
    float* sQ    = sm + OFF_S0;     // alias: Q staged here only for A-frags
    float* sScr  = sm + OFF_SCR;

    const int tid  = threadIdx.x;
    const int lane = tid & 31;
    const int wid  = tid >> 5;      // warp = column block w (16 cols)
    const int q0   = blockIdx.x * QT;

    const int tr = lane >> 2;     // 0..7
    const int tc = lane & 3;      // 0..3

    const uint32_t smemBase = (uint32_t)__cvta_generic_to_shared(sm);
    const uint32_t mbarA  = smemBase + OFF_MBAR * 4;
    const uint32_t sblobA = smemBase + OFF_BLOB * 4;

    // ldmatrix lane offset (bytes) within a blob: rows 16*wid..+15, k lo/hi
    const uint32_t boff = (uint32_t)(CT * 4) +
        (uint32_t)(((16 * wid + ((lane >> 4) & 1) * 8 + (lane & 7)) * MUS
                    + ((lane >> 3) & 1) * 4) * 4);

    // hm2 quad word offset
    const int hmoff = 16 * wid + 4 * tc;

    // score store word offsets for the 4 rows R = 16m+8h+tr
    int Wr[2][2];
#pragma unroll
    for (int m = 0; m < 2; m++)
#pragma unroll
        for (int h = 0; h < 2; h++) {
            int R = 16 * m + 8 * h + tr;
            Wr[m][h] = (16 * (wid ^ (R & 1)) + 4 * tc + 2048 - 4 * R) & 127;
        }

    auto issue_chunk = [&](int chunk) {
        if (tid == 0) {
            int buf = chunk & 1;
            uint32_t mb = mbarA + (uint32_t)(buf * 8);
            mbar_expect_tx(mb, BUFBYTES);
            bulk_g2s(sblobA + (uint32_t)buf * BUFBYTES,
                     g_blob + (size_t)chunk * BUFFLOATS, BUFBYTES, mb);
        }
    };

    // ---- prologue: stage Q (aliased region), init mbarriers ----
    for (int idx = tid; idx < QT * DK; idx += 256) {
        int q = idx >> 6, k = idx & 63;
        sQ[q * MUS + k] = q_tilde[(size_t)(q0 + q) * DK + k];
    }
    if (tid == 0) {
        mbar_init(mbarA, 1);
        mbar_init(mbarA + 8, 1);
    }
    __syncthreads();   // sQ + mbarrier init visible
    issue_chunk(0);

    // A fragments for BOTH m-tiles (rows 16m+tr / +8), resident all chunks
    uint32_t af[2][8][4];
#pragma unroll
    for (int m = 0; m < 2; m++) {
        const float* qa = sQ + (16 * m + tr) * MUS + tc;
#pragma unroll
        for (int kt = 0; kt < 8; kt++) {
            af[m][kt][0] = to_tf32(qa[8 * kt]);
            af[m][kt][1] = to_tf32(qa[8 * MUS + 8 * kt]);
            af[m][kt][2] = to_tf32(qa[8 * kt + 4]);
            af[m][kt][3] = to_tf32(qa[8 * MUS + 8 * kt + 4]);
        }
    }
    // sQ dead from here; first sS0 write is after the first in-loop barrier.

    // selection state: warp wid owns queries 4*wid + r
    unsigned cu[4]; int ci[4]; float thr[4]; unsigned thrU[4];
    const unsigned NEGINF_U = fenc(-INFINITY);
#pragma unroll
    for (int r = 0; r < 4; r++) {
        cu[r] = NEGINF_U; ci[r] = 0; thr[r] = -INFINITY; thrU[r] = NEGINF_U;
    }

    // deferred selection of one chunk's score tile (reads sbuf)
    auto select_chunk = [&](const float* sbuf, int base) {
        float4 f[4]; float lmax[4];
#pragma unroll
        for (int r = 0; r < 4; r++) {
            const float* row = sbuf + (4 * wid + r) * SSTR;
            f[r] = *reinterpret_cast<const float4*>(row + 4 * lane);
            lmax[r] = fmaxf(fmaxf(f[r].x, f[r].y), fmaxf(f[r].z, f[r].w));
        }
        bool anyc = (lmax[0] > thr[0]) | (lmax[1] > thr[1]) |
                    (lmax[2] > thr[2]) | (lmax[3] > thr[3]);
        if (!__ballot_sync(FULLMASK, anyc)) return;
#pragma unroll
        for (int r = 0; r < 4; r++) {
            const int row = 4 * wid + r;
            unsigned m = __ballot_sync(FULLMASK, lmax[r] > thr[r]);
            while (m) {
                int src = __ffs(m) - 1;
                m &= m - 1;
                float g0 = __shfl_sync(FULLMASK, f[r].x, src);
                float g1 = __shfl_sync(FULLMASK, f[r].y, src);
                float g2 = __shfl_sync(FULLMASK, f[r].z, src);
                float g3 = __shfl_sync(FULLMASK, f[r].w, src);
                // decode stored column: X=(4src+4row)&127; w=(X>>4)^(row&1)
                int X = (4 * src + 4 * row) & 127;
                int wdec = ((X >> 4) ^ (row & 1));
                int colb = 16 * wdec + ((X >> 2) & 3) * 2;
                int ib = base + colb;
#pragma unroll
                for (int j = 0; j < 4; j++) {
                    float nv = (j == 0) ? g0 : (j == 1) ? g1 : (j == 2) ? g2 : g3;
                    if (nv > thr[r]) {
                        unsigned bl = __ballot_sync(FULLMASK, cu[r] == thrU[r]);
                        int ml = __ffs(bl) - 1;
                        if (lane == ml) {
                            cu[r] = fenc(nv);
                            ci[r] = ib + 8 * (j >> 1) + (j & 1);
                        }
                        thrU[r] = redux_min_u32(cu[r]);
                        thr[r]  = fdec(thrU[r]);
                    }
                }
            }
        }
    };

    for (int ch = 0; ch < NCHUNK; ++ch) {
        const int buf = ch & 1;
        mbar_wait(mbarA + (uint32_t)(buf * 8), (ch >> 1) & 1);
        __syncthreads();   // buffer visible; stores(ch-1), select(ch-2) done;
                           // GEMM(ch-1) reads of mu[(ch+1)&1] done
        if (ch + 1 < NCHUNK) issue_chunk(ch + 1);

        const uint32_t bufB = sblobA + (uint32_t)buf * BUFBYTES;
        const float*   hbp  = sBlob + buf * BUFFLOATS;

        // ---- tensor-core GEMM: warp tile 32q x 16c ----
        float acc[2][2][4];
#pragma unroll
        for (int m = 0; m < 2; m++)
#pragma unroll
            for (int nt = 0; nt < 2; nt++)
#pragma unroll
                for (int j = 0; j < 4; j++) acc[m][nt][j] = 0.f;

        const uint32_t a0 = bufB + boff;
#pragma unroll
        for (int kt = 0; kt < 8; kt++) {
            uint32_t r0, r1, r2, r3;
            ldsm_x4(a0 + kt * 32, r0, r1, r2, r3);
            mma_tf32(acc[0][0], af[0][kt], r0, r1);
            mma_tf32(acc[0][1], af[0][kt], r2, r3);
            mma_tf32(acc[1][0], af[1][kt], r0, r1);
            mma_tf32(acc[1][1], af[1][kt], r2, r3);
        }

        // ---- deferred selection of previous chunk (overlaps GEMM latency) ----
        if (ch > 0)
            select_chunk(sS + ((ch - 1) & 1) * SBUF, (ch - 1) * CT);

        // ---- scores -> sS[ch&1] (row-shifted layout, 4x STS.128) ----
        {
            float* sb = sS + buf * SBUF;
            float4 hm = *reinterpret_cast<const float4*>(hbp + hmoff);
#pragma unroll
            for (int m = 0; m < 2; m++)
#pragma unroll
                for (int h = 0; h < 2; h++) {
                    int R = 16 * m + 8 * h + tr;
                    float4 v;
                    v.x = acc[m][0][2 * h]     - hm.x;
                    v.y = acc[m][0][2 * h + 1] - hm.y;
                    v.z = acc[m][1][2 * h]     - hm.z;
                    v.w = acc[m][1][2 * h + 1] - hm.w;
                    *reinterpret_cast<float4*>(sb + R * SSTR + Wr[m][h]) = v;
                }
        }
    }

    // final chunk's selection
    __syncthreads();
    select_chunk(sS + ((NCHUNK - 1) & 1) * SBUF, (NCHUNK - 1) * CT);

    // publish top-32 indices per query into sS0 (final select read sS1)
    int* sTopI = reinterpret_cast<int*>(sS);
#pragma unroll
    for (int r = 0; r < 4; r++) {
        int q = 4 * wid + r;
        sTopI[q * 32 + lane] = ci[r];
    }
    __syncthreads();

    const float sigma  = sig[0];
    const float inv_s2 = 1.f / (sigma * sigma);
    const float bgate  = Wgb[0];
    const float gw     = gpw[0];

    float* myW = sScr + wid * 64;
    int*   myI = reinterpret_cast<int*>(myW + 32);

    // ---- epilogue: EXACT rescore + softmax + gathers + gate ----
#pragma unroll
    for (int round = 0; round < 4; ++round) {
        int q   = wid + 8 * round;
        int qg2 = q0 + q;

        int idx = sTopI[q * 32 + lane];

        const float4* mrow = reinterpret_cast<const float4*>(mu + (size_t)idx * DK);
        const float4* qrow = reinterpret_cast<const float4*>(q_tilde + (size_t)qg2 * DK);
        float d0 = 0.f, d1 = 0.f, d2 = 0.f, d3 = 0.f;
#pragma unroll
        for (int j = 0; j < 16; j += 4) {
            float4 m0 = mrow[j],     qv0 = qrow[j];
            float4 m1 = mrow[j + 1], qv1 = qrow[j + 1];
            float4 m2 = mrow[j + 2], qv2 = qrow[j + 2];
            float4 m3 = mrow[j + 3], qv3 = qrow[j + 3];
            d0 += m0.x * qv0.x + m0.y * qv0.y + m0.z * qv0.z + m0.w * qv0.w;
            d1 += m1.x * qv1.x + m1.y * qv1.y + m1.z * qv1.z + m1.w * qv1.w;
            d2 += m2.x * qv2.x + m2.y * qv2.y + m2.z * qv2.z + m2.w * qv2.w;
            d3 += m3.x * qv3.x + m3.y * qv3.y + m3.z * qv3.z + m3.w * qv3.w;
        }
        float s = ((d0 + d1) + (d2 + d3) - g_hm2[idx]) * inv_s2;

        float mx = s;
#pragma unroll
        for (int off = 16; off; off >>= 1)
            mx = fmaxf(mx, __shfl_xor_sync(FULLMASK, mx, off));
        float e = __expf(s - mx);
        float se = e;
#pragma unroll
        for (int off = 16; off; off >>= 1)
            se += __shfl_xor_sync(FULLMASK, se, off);
        float wgt = e / se;

        myW[lane] = wgt;
        myI[lane] = idx;
        __syncwarp();

        float4 acc = make_float4(0.f, 0.f, 0.f, 0.f);
#pragma unroll 4
        for (int k = 0; k < 32; k++) {
            float wk = myW[k];
            size_t row = (size_t)myI[k];
            float4 v = reinterpret_cast<const float4*>(V + row * 128)[lane];
            acc.x += wk * v.x; acc.y += wk * v.y;
            acc.z += wk * v.z; acc.w += wk * v.w;
        }

        float re = 0.f;
        if (lane < 4) {
            for (int k = 0; k < 32; k++)
                re += myW[k] * E[(size_t)myI[k] * 4 + lane];
        }

        const float4 wv = reinterpret_cast<const float4*>(Wg + 256)[lane];
        float tot = acc.x * wv.x + acc.y * wv.y + acc.z * wv.z + acc.w * wv.w;
        const float* xq = x + (size_t)qg2 * 256;
#pragma unroll
        for (int u = 0; u < 8; u++) {
            int t = lane + 32 * u;
            tot += xq[t] * Wg[t];
        }
#pragma unroll
        for (int off = 16; off; off >>= 1)
            tot += __shfl_xor_sync(FULLMASK, tot, off);

        reinterpret_cast<float4*>(out + RV_OFF + (size_t)qg2 * 128)[lane] = acc;
        if (lane < 4) out[RE_OFF + (size_t)qg2 * 4 + lane] = re;
        if (lane == 0) {
            float z = tot + bgate + gw * g_prior[qg2];
            out[G_OFF + qg2] = 1.f / (1.f + __expf(-z));
        }
        __syncwarp();
    }
}

extern "C" void kernel_launch(void* const* d_in, const int* in_sizes, int n_in,
                              void* d_out, int out_size) {
    (void)in_sizes; (void)n_in; (void)out_size;
    const float* x   = (const float*)d_in[0];
    const float* qt  = (const float*)d_in[1];
    const float* gp  = (const float*)d_in[2];
    const float* mu  = (const float*)d_in[3];
    const float* V   = (const float*)d_in[4];
    const float* E   = (const float*)d_in[5];
    const float* sg  = (const float*)d_in[6];
    const float* Wg  = (const float*)d_in[7];
    const float* Wb  = (const float*)d_in[8];
    const float* gw  = (const float*)d_in[9];

    prep_kernel<<<NC / 256, 256>>>(mu);

    const int smem_bytes = SMEM_FLOATS * 4;   // 106560
    cudaFuncSetAttribute(ma_kernel, cudaFuncAttributeMaxDynamicSharedMemorySize,
                         smem_bytes);
    ma_kernel<<<NQ / QT, 256, smem_bytes>>>(x, qt, gp, mu, V, E, sg, Wg, Wb, gw,
                                            (float*)d_out);
}